// round 5
// baseline (speedup 1.0000x reference)
#include <cuda_runtime.h>
#include <math.h>

// Problem shape (fixed per reference): h is (32, 4096, 1024) fp32.
#define BATCH   32
#define SEQ     4096
#define HID     1024
#define W       32          // window rows
#define WSTART  2032        // 4096/2 - 16
#define NCH     8           // d-chunks
#define CHUNK   128         // HID / NCH
#define NPAIR   528         // 32*33/2 upper-triangle incl diag
#define SWEEPS  6

// Scratch: per-batch, per-chunk partial Gram (upper triangle), fp32.
__device__ float g_part[BATCH][NCH][NPAIR];

// ---------------------------------------------------------------------------
// Kernel 1: partial raw Gram R = W W^T over a 128-column chunk.
// grid = (NCH, BATCH), block = 544 (17 warps; 528 pair threads).
// ---------------------------------------------------------------------------
__global__ void __launch_bounds__(544) gram_kernel(const float* __restrict__ h) {
    const int chunk = blockIdx.x;
    const int b     = blockIdx.y;
    __shared__ float As[W][CHUNK + 1];   // pad -> conflict-free column reads

    const int tid = threadIdx.x;
    const float* base = h + ((size_t)b * SEQ + WSTART) * HID + (size_t)chunk * CHUNK;

    // Stage tile: 32 rows x 128 cols = 1024 float4 loads.
    for (int idx = tid; idx < W * (CHUNK / 4); idx += blockDim.x) {
        int row = idx >> 5;           // /32 float4 per row
        int c4  = idx & 31;
        float4 v = *(const float4*)(base + (size_t)row * HID + c4 * 4);
        As[row][c4 * 4 + 0] = v.x;
        As[row][c4 * 4 + 1] = v.y;
        As[row][c4 * 4 + 2] = v.z;
        As[row][c4 * 4 + 3] = v.w;
    }
    __syncthreads();

    if (tid < NPAIR) {
        // decode upper-triangle pair (i, j), i <= j
        int i = 0, rem = tid;
        while (rem >= W - i) { rem -= W - i; i++; }
        int j = i + rem;

        const float* ai = As[i];
        const float* aj = As[j];
        float acc = 0.f;
        #pragma unroll 8
        for (int d = 0; d < CHUNK; d++) acc = fmaf(ai[d], aj[d], acc);
        g_part[b][chunk][tid] = acc;
    }
}

// ---------------------------------------------------------------------------
// One Jacobi round with xor-pair mask T (compile-time).
// Lane l owns column l in local view b[k] = A[k ^ l][l].
//   - own diag = b[0], pair off-diag = b[T], partner lane = l ^ T.
//   - Each lane computes ONE rotation (its own pair), coefficients of other
//     pairs arrive via shfl_xor.
// Row stage:  B = J^T A  (pairs of local regs (k, k^T)).
// Col stage:  A' = B J   (partner's row-stage values via shfl_xor(., T)).
// All register indices compile-time; no smem, no barriers.
// ---------------------------------------------------------------------------
template<int T>
__device__ __forceinline__ void jacobi_round(float (&b)[32], int lane) {
    const unsigned FULL = 0xFFFFFFFFu;
    const int  h     = lane ^ T;
    const bool is_lo = lane < h;

    float own = b[0];
    float oth = __shfl_xor_sync(FULL, own, T);
    float apq = b[T];
    float app = is_lo ? own : oth;
    float aqq = is_lo ? oth : own;

    float c, s;
    if (fabsf(apq) > 1e-12f) {
        float tau = __fdividef((aqq - app) * 0.5f, apq);
        float tt  = __fdividef(1.0f, fabsf(tau) + sqrtf(fmaf(tau, tau, 1.0f)));
        tt = copysignf(tt, tau);
        c = rsqrtf(fmaf(tt, tt, 1.0f));
        s = tt * c;
    } else {
        c = 1.0f; s = 0.0f;
    }
    const float ac = c;
    const float bc = is_lo ? -s : s;

    // --- row stage: B[r][l] over local pairs (k, k^T) ---
    #pragma unroll
    for (int k = 0; k < 32; k++) {
        if (k < (k ^ T)) {
            float ar = __shfl_xor_sync(FULL, ac, k);
            float br = __shfl_xor_sync(FULL, bc, k);
            float t1 = fmaf(ar, b[k],     br * b[k ^ T]);
            float t2 = fmaf(ar, b[k ^ T], -br * b[k]);
            b[k]     = t1;
            b[k ^ T] = t2;
        }
    }
    // --- col stage: A'[.][l] = ac*B[.][l] + bc*B[.][l^T] ---
    #pragma unroll
    for (int k = 0; k < 32; k++) {
        if (k < (k ^ T)) {
            float w1 = __shfl_xor_sync(FULL, b[k ^ T], T);
            float w2 = __shfl_xor_sync(FULL, b[k],     T);
            b[k]     = fmaf(ac, b[k],     bc * w1);
            b[k ^ T] = fmaf(ac, b[k ^ T], bc * w2);
        }
    }
}

__device__ __forceinline__ void jacobi_sweep(float (&b)[32], int lane) {
    jacobi_round< 1>(b, lane); jacobi_round< 2>(b, lane);
    jacobi_round< 3>(b, lane); jacobi_round< 4>(b, lane);
    jacobi_round< 5>(b, lane); jacobi_round< 6>(b, lane);
    jacobi_round< 7>(b, lane); jacobi_round< 8>(b, lane);
    jacobi_round< 9>(b, lane); jacobi_round<10>(b, lane);
    jacobi_round<11>(b, lane); jacobi_round<12>(b, lane);
    jacobi_round<13>(b, lane); jacobi_round<14>(b, lane);
    jacobi_round<15>(b, lane); jacobi_round<16>(b, lane);
    jacobi_round<17>(b, lane); jacobi_round<18>(b, lane);
    jacobi_round<19>(b, lane); jacobi_round<20>(b, lane);
    jacobi_round<21>(b, lane); jacobi_round<22>(b, lane);
    jacobi_round<23>(b, lane); jacobi_round<24>(b, lane);
    jacobi_round<25>(b, lane); jacobi_round<26>(b, lane);
    jacobi_round<27>(b, lane); jacobi_round<28>(b, lane);
    jacobi_round<29>(b, lane); jacobi_round<30>(b, lane);
    jacobi_round<31>(b, lane);
}

// ---------------------------------------------------------------------------
// Kernel 2: per-batch — prologue (256 threads): reduce partials (fp64),
// center+normalize to C (fp32). Then warp 0 runs a register-resident,
// barrier-free Jacobi eigensolve; warps 1-7 retire.
// grid padded to 148 (idle blocks exit) to avoid low-grid issue throttle.
// ---------------------------------------------------------------------------
__global__ void __launch_bounds__(256) eig_kernel(float* __restrict__ out, int n) {
    const int b = blockIdx.x;
    if (b >= BATCH) return;
    const int tid  = threadIdx.x;
    const int lane = tid & 31;
    const int wid  = tid >> 5;

    __shared__ double Gs[W][W + 1];
    __shared__ double rsum[W];
    __shared__ double Ssum;
    __shared__ double traceSh;
    __shared__ float  dinv[W];
    __shared__ float  Abuf[W][W + 1];
    __shared__ float  lam[W];
    __shared__ float  evals[3];   // e0, e7, e8

    // --- reduce chunk partials in double, mirror to full symmetric matrix ---
    for (int t = tid; t < NPAIR; t += 256) {
        double g = 0.0;
        #pragma unroll
        for (int c = 0; c < NCH; c++) g += (double)g_part[b][c][t];
        int i = 0, rem = t;
        while (rem >= W - i) { rem -= W - i; i++; }
        int j = i + rem;
        Gs[i][j] = g;
        Gs[j][i] = g;
    }
    __syncthreads();

    // --- row sums and grand sum (centering terms) ---
    if (tid < W) {
        double r = 0.0;
        #pragma unroll
        for (int j = 0; j < W; j++) r += Gs[tid][j];
        rsum[tid] = r;
    }
    __syncthreads();
    if (tid == 0) {
        double s = 0.0;
        #pragma unroll
        for (int i = 0; i < W; i++) s += rsum[i];
        Ssum = s;
    }
    __syncthreads();

    const double Sq = Ssum * (1.0 / 1024.0);   // S / 32^2

    // --- inverse (norm + eps) per row; centered diag = R_ii - r_i/16 + S/1024 ---
    if (tid < W) {
        double di = Gs[tid][tid] - rsum[tid] * (1.0 / 16.0) + Sq;
        if (di < 0.0) di = 0.0;
        dinv[tid] = (float)(1.0 / (sqrt(di) + 1e-8));
    }
    __syncthreads();

    // --- build normalized covariance C in fp32 (4 elements per thread) ---
    {
        #pragma unroll
        for (int e = 0; e < 4; e++) {
            int idx = tid + e * 256;
            int k = idx >> 5, l = idx & 31;
            double gc = Gs[k][l] - rsum[k] * (1.0 / 32.0) - rsum[l] * (1.0 / 32.0) + Sq;
            Abuf[k][l] = (float)gc * dinv[k] * dinv[l];
        }
    }
    __syncthreads();
    if (tid == 0) {
        double tr = 0.0;
        #pragma unroll
        for (int i = 0; i < W; i++) tr += (double)Abuf[i][i];
        traceSh = tr;
    }
    __syncthreads();

    // --- warps 1..7 are done; warp 0 owns the eigensolve ---
    if (wid != 0) return;

    // Load local xor view: b[k] = A[k ^ lane][lane].
    float bk[32];
    #pragma unroll
    for (int k = 0; k < 32; k++) bk[k] = Abuf[k ^ lane][lane];

    #pragma unroll 1
    for (int sw = 0; sw < SWEEPS; sw++)
        jacobi_sweep(bk, lane);

    // Diagonal (eigenvalues): A[lane][lane] = bk[0].
    lam[lane] = bk[0];
    __syncwarp();

    {
        float v = lam[lane];
        int rank = 0;
        #pragma unroll
        for (int u = 0; u < W; u++) {
            float vu = lam[u];
            if (vu > v || (vu == v && u < lane)) rank++;
        }
        if (rank == 0) evals[0] = v;
        if (rank == 7) evals[1] = v;
        if (rank == 8) evals[2] = v;
    }
    __syncwarp();

    if (lane == 0) {
        float e0 = evals[0], e7 = evals[1], e8 = evals[2];
        float gap   = e7 - e8;
        float decay = (e0 - e8) * (1.0f / 9.0f);
        float lmin  = e8 + 1e-8f;
        float topo  = gap / (decay + 1e-8f);
        if (topo < 0.f) topo = 0.f;
        float geo   = lmin / ((float)traceSh + 1e-8f);
        float gcve  = topo + geo;
        out[b]         = gcve;   // gcve_scores
        out[n + b]     = 0.0f;   // fracture_scores
        out[2 * n + b] = gcve;   // total_pressure
    }
}

// ---------------------------------------------------------------------------
extern "C" void kernel_launch(void* const* d_in, const int* in_sizes, int n_in,
                              void* d_out, int out_size) {
    const float* h = (const float*)d_in[0];
    float* out = (float*)d_out;
    int n = out_size / 3;   // 32

    dim3 g1(NCH, BATCH);
    gram_kernel<<<g1, 544>>>(h);
    eig_kernel<<<148, 256>>>(out, n);   // blocks >= 32 exit immediately
}

// round 6
// speedup vs baseline: 1.9499x; 1.9499x over previous
#include <cuda_runtime.h>
#include <math.h>

// Problem shape (fixed per reference): h is (32, 4096, 1024) fp32.
#define BATCH   32
#define SEQ     4096
#define HID     1024
#define W       32          // window rows
#define WSTART  2032        // 4096/2 - 16
#define NCH     8           // d-chunks
#define CHUNK   128         // HID / NCH
#define NPAIR   528         // 32*33/2 upper-triangle incl diag
#define FULLM   0xFFFFFFFFu

// Scratch: per-batch, per-chunk partial Gram (upper triangle), fp32.
__device__ float g_part[BATCH][NCH][NPAIR];

// ---------------------------------------------------------------------------
// Kernel 1: partial raw Gram R = W W^T over a 128-column chunk.
// grid = (NCH, BATCH), block = 544 (17 warps; 528 pair threads).
// ---------------------------------------------------------------------------
__global__ void __launch_bounds__(544) gram_kernel(const float* __restrict__ h) {
    const int chunk = blockIdx.x;
    const int b     = blockIdx.y;
    __shared__ float As[W][CHUNK + 1];   // pad -> conflict-free column reads

    const int tid = threadIdx.x;
    const float* base = h + ((size_t)b * SEQ + WSTART) * HID + (size_t)chunk * CHUNK;

    for (int idx = tid; idx < W * (CHUNK / 4); idx += blockDim.x) {
        int row = idx >> 5;
        int c4  = idx & 31;
        float4 v = *(const float4*)(base + (size_t)row * HID + c4 * 4);
        As[row][c4 * 4 + 0] = v.x;
        As[row][c4 * 4 + 1] = v.y;
        As[row][c4 * 4 + 2] = v.z;
        As[row][c4 * 4 + 3] = v.w;
    }
    __syncthreads();

    if (tid < NPAIR) {
        int i = 0, rem = tid;
        while (rem >= W - i) { rem -= W - i; i++; }
        int j = i + rem;

        const float* ai = As[i];
        const float* aj = As[j];
        float acc = 0.f;
        #pragma unroll 8
        for (int d = 0; d < CHUNK; d++) acc = fmaf(ai[d], aj[d], acc);
        g_part[b][chunk][tid] = acc;
    }
}

// ---------------------------------------------------------------------------
// Warp helpers
// ---------------------------------------------------------------------------
__device__ __forceinline__ float wsum32(float v) {
    #pragma unroll
    for (int o = 16; o; o >>= 1) v += __shfl_xor_sync(FULLM, v, o);
    return v;
}
__device__ __forceinline__ float wmin32(float v) {
    #pragma unroll
    for (int o = 16; o; o >>= 1) v = fminf(v, __shfl_xor_sync(FULLM, v, o));
    return v;
}
__device__ __forceinline__ float wmax32(float v) {
    #pragma unroll
    for (int o = 16; o; o >>= 1) v = fmaxf(v, __shfl_xor_sync(FULLM, v, o));
    return v;
}

// Dynamic select a[k] (runtime k) from a static register array: 31-SEL mux tree.
__device__ __forceinline__ float sel32(const float (&a)[32], int k) {
    float t16[16], t8[8], t4[4], t2[2];
    #pragma unroll
    for (int j = 0; j < 16; j++) t16[j] = (k & 16) ? a[j + 16] : a[j];
    #pragma unroll
    for (int j = 0; j < 8;  j++) t8[j]  = (k & 8)  ? t16[j + 8] : t16[j];
    #pragma unroll
    for (int j = 0; j < 4;  j++) t4[j]  = (k & 4)  ? t8[j + 4]  : t8[j];
    #pragma unroll
    for (int j = 0; j < 2;  j++) t2[j]  = (k & 2)  ? t4[j + 2]  : t4[j];
    return (k & 1) ? t2[1] : t2[0];
}

// Sturm count for 32x32 tridiagonal (diag dS, squared offdiag e2S): #eigs < x.
__device__ __forceinline__ int sturm32(const float* __restrict__ dS,
                                       const float* __restrict__ e2S, float x) {
    float dp = dS[0] - x;
    int cnt = (dp < 0.f) ? 1 : 0;
    #pragma unroll
    for (int i = 1; i < 32; i++) {
        float den = copysignf(fmaxf(fabsf(dp), 1e-25f), dp);
        dp = (dS[i] - x) - __fdividef(e2S[i - 1], den);
        cnt += (dp < 0.f) ? 1 : 0;
    }
    return cnt;
}

// ---------------------------------------------------------------------------
// Kernel 2: per-batch — prologue (256 threads): reduce partials (fp64),
// center+normalize to C (fp32). Warp 0 then: Householder tridiagonalization
// (register-resident rows) + multi-point Sturm bisection for lambda 0/7/8.
// ---------------------------------------------------------------------------
__global__ void __launch_bounds__(256) eig_kernel(float* __restrict__ out, int n) {
    const int b = blockIdx.x;
    if (b >= BATCH) return;
    const int tid  = threadIdx.x;
    const int lane = tid & 31;
    const int wid  = tid >> 5;

    __shared__ double Gs[W][W + 1];
    __shared__ double rsum[W];
    __shared__ double Ssum;
    __shared__ double traceSh;
    __shared__ float  dinv[W];
    __shared__ float  Abuf[W][W + 1];
    __shared__ float  dS[W];        // tridiagonal diag
    __shared__ float  e2S[W];       // offdiag^2  (index 0..30; [31]=0)
    __shared__ float  eaS[W];       // |offdiag|  (index 0..30; [31]=0)

    // --- reduce chunk partials in double, mirror to full symmetric matrix ---
    for (int t = tid; t < NPAIR; t += 256) {
        double g = 0.0;
        #pragma unroll
        for (int c = 0; c < NCH; c++) g += (double)g_part[b][c][t];
        int i = 0, rem = t;
        while (rem >= W - i) { rem -= W - i; i++; }
        int j = i + rem;
        Gs[i][j] = g;
        Gs[j][i] = g;
    }
    __syncthreads();

    if (tid < W) {
        double r = 0.0;
        #pragma unroll
        for (int j = 0; j < W; j++) r += Gs[tid][j];
        rsum[tid] = r;
    }
    __syncthreads();
    if (tid == 0) {
        double s = 0.0;
        #pragma unroll
        for (int i = 0; i < W; i++) s += rsum[i];
        Ssum = s;
    }
    __syncthreads();

    const double Sq = Ssum * (1.0 / 1024.0);   // S / 32^2

    if (tid < W) {
        double di = Gs[tid][tid] - rsum[tid] * (1.0 / 16.0) + Sq;
        if (di < 0.0) di = 0.0;
        dinv[tid] = (float)(1.0 / (sqrt(di) + 1e-8));
    }
    __syncthreads();

    {
        #pragma unroll
        for (int e = 0; e < 4; e++) {
            int idx = tid + e * 256;
            int k = idx >> 5, l = idx & 31;
            double gc = Gs[k][l] - rsum[k] * (1.0 / 32.0) - rsum[l] * (1.0 / 32.0) + Sq;
            Abuf[k][l] = (float)gc * dinv[k] * dinv[l];
        }
    }
    __syncthreads();
    if (tid == 0) {
        double tr = 0.0;
        #pragma unroll
        for (int i = 0; i < W; i++) tr += (double)Abuf[i][i];
        traceSh = tr;
    }
    __syncthreads();

    if (wid != 0) return;   // warps 1..7 retire; warp 0 owns the eigensolve

    // ====================== Householder tridiagonalization ==================
    // Lane i holds row i of A in registers a[0..31] (static indices only).
    float a[32];
    #pragma unroll
    for (int j = 0; j < 32; j++) a[j] = Abuf[lane][j];

    #pragma unroll 1
    for (int k = 0; k < 30; k++) {
        const int m = k + 1;
        // column k: x_i = A[i][k] = own row element k (mux tree, runtime k)
        float x = sel32(a, k);
        if (lane < m) x = 0.f;
        float sig = wsum32(x * x);
        float x0  = __shfl_sync(FULLM, x, m);
        float nrm = sqrtf(sig);
        float alpha = -copysignf(nrm, x0);
        // beta = 2 / v^T v ;  v^T v = 2*sig + 2*|x0|*nrm  (no cancellation)
        float beta = (sig > 1e-30f) ? __fdividef(1.f, sig + fabsf(x0) * nrm) : 0.f;
        float vi = (lane == m) ? x - alpha : x;

        // broadcast v (static-index shfl)
        float vb[32];
        #pragma unroll
        for (int j = 0; j < 32; j++) vb[j] = __shfl_sync(FULLM, vi, j);

        // p = beta * A v (restricted to rows >= m; v_j = 0 for j < m)
        float p = 0.f;
        #pragma unroll
        for (int j = 0; j < 32; j++) p = fmaf(a[j], vb[j], p);
        p = (lane >= m) ? p * beta : 0.f;

        float vtp = wsum32(vi * p);
        float Kc  = 0.5f * beta * vtp;
        float q   = p - Kc * vi;

        // A -= v q^T + q v^T
        #pragma unroll
        for (int j = 0; j < 32; j++) {
            float qb = __shfl_sync(FULLM, q, j);
            a[j] -= vi * qb + q * vb[j];
        }

        if (lane == 0) { e2S[k] = alpha * alpha; eaS[k] = fabsf(alpha); }
    }
    {   // last offdiagonal e_30 = A[30][31]
        float e30 = __shfl_sync(FULLM, a[31], 30);
        if (lane == 0) {
            e2S[30] = e30 * e30; eaS[30] = fabsf(e30);
            e2S[31] = 0.f;       eaS[31] = 0.f;
        }
    }
    dS[lane] = sel32(a, lane);   // diagonal
    __syncwarp();

    // ====================== multi-point Sturm bisection =====================
    // Gershgorin bracket
    float eprev = (lane > 0) ? eaS[lane - 1] : 0.f;
    float rad   = eaS[lane] + eprev;
    float lo = wmin32(dS[lane] - rad);
    float hi = wmax32(dS[lane] + rad);

    // 3 targets x 10 lanes: ascending eigen indices 31 (e0), 24 (e7), 23 (e8).
    int g = lane / 10; if (g > 2) g = 2;
    const int m = lane - g * 10;                 // 0..9 (lanes 30,31: 10,11 -> ignored)
    const int idx = (g == 0) ? 31 : (g == 1) ? 24 : 23;

    #pragma unroll 1
    for (int r = 0; r < 8; r++) {
        float w  = (hi - lo) * (1.0f / 11.0f);
        float xx = lo + w * (float)(m + 1);
        int   cnt  = sturm32(dS, e2S, xx);
        unsigned bal = __ballot_sync(FULLM, cnt <= idx);   // x left of lambda_idx
        unsigned gb  = (bal >> (g * 10)) & 0x3FFu;
        int mstar = 31 - __clz(gb);                        // -1..9
        lo = lo + w * (float)(mstar + 1);
        hi = lo + w;
    }
    float lam = 0.5f * (lo + hi);
    float e0 = __shfl_sync(FULLM, lam, 0);
    float e7 = __shfl_sync(FULLM, lam, 10);
    float e8 = __shfl_sync(FULLM, lam, 20);

    if (lane == 0) {
        float gap   = e7 - e8;
        float decay = (e0 - e8) * (1.0f / 9.0f);
        float lmin  = e8 + 1e-8f;
        float topo  = gap / (decay + 1e-8f);
        if (topo < 0.f) topo = 0.f;
        float geo   = lmin / ((float)traceSh + 1e-8f);
        float gcve  = topo + geo;
        out[b]         = gcve;   // gcve_scores
        out[n + b]     = 0.0f;   // fracture_scores
        out[2 * n + b] = gcve;   // total_pressure
    }
}

// ---------------------------------------------------------------------------
extern "C" void kernel_launch(void* const* d_in, const int* in_sizes, int n_in,
                              void* d_out, int out_size) {
    const float* h = (const float*)d_in[0];
    float* out = (float*)d_out;
    int n = out_size / 3;   // 32

    dim3 g1(NCH, BATCH);
    gram_kernel<<<g1, 544>>>(h);
    eig_kernel<<<148, 256>>>(out, n);   // blocks >= 32 exit immediately
}

// round 7
// speedup vs baseline: 2.4164x; 1.2393x over previous
#include <cuda_runtime.h>
#include <math.h>

// Problem shape (fixed per reference): h is (32, 4096, 1024) fp32.
#define BATCH   32
#define SEQ     4096
#define HID     1024
#define W       32          // window rows
#define WSTART  2032        // 4096/2 - 16
#define NCH     8           // d-chunks
#define CHUNK   128         // HID / NCH
#define NPAIR   528         // 32*33/2 upper-triangle incl diag
#define FULLM   0xFFFFFFFFu

// Scratch: per-batch, per-chunk partial Gram (upper triangle), fp32.
__device__ float g_part[BATCH][NCH][NPAIR];

// ---------------------------------------------------------------------------
// Kernel 1: partial raw Gram R = W W^T over a 128-column chunk.
// grid = (NCH, BATCH), block = 544 (17 warps; 528 pair threads).
// ---------------------------------------------------------------------------
__global__ void __launch_bounds__(544) gram_kernel(const float* __restrict__ h) {
    const int chunk = blockIdx.x;
    const int b     = blockIdx.y;
    __shared__ float As[W][CHUNK + 1];   // pad -> conflict-free column reads

    const int tid = threadIdx.x;
    const float* base = h + ((size_t)b * SEQ + WSTART) * HID + (size_t)chunk * CHUNK;

    for (int idx = tid; idx < W * (CHUNK / 4); idx += blockDim.x) {
        int row = idx >> 5;
        int c4  = idx & 31;
        float4 v = *(const float4*)(base + (size_t)row * HID + c4 * 4);
        As[row][c4 * 4 + 0] = v.x;
        As[row][c4 * 4 + 1] = v.y;
        As[row][c4 * 4 + 2] = v.z;
        As[row][c4 * 4 + 3] = v.w;
    }
    __syncthreads();

    if (tid < NPAIR) {
        int i = 0, rem = tid;
        while (rem >= W - i) { rem -= W - i; i++; }
        int j = i + rem;

        const float* ai = As[i];
        const float* aj = As[j];
        float acc = 0.f;
        #pragma unroll 8
        for (int d = 0; d < CHUNK; d++) acc = fmaf(ai[d], aj[d], acc);
        g_part[b][chunk][tid] = acc;
    }
}

// ---------------------------------------------------------------------------
// Warp helpers
// ---------------------------------------------------------------------------
__device__ __forceinline__ float wsum32(float v) {
    #pragma unroll
    for (int o = 16; o; o >>= 1) v += __shfl_xor_sync(FULLM, v, o);
    return v;
}
__device__ __forceinline__ float wmin32(float v) {
    #pragma unroll
    for (int o = 16; o; o >>= 1) v = fminf(v, __shfl_xor_sync(FULLM, v, o));
    return v;
}
__device__ __forceinline__ float wmax32(float v) {
    #pragma unroll
    for (int o = 16; o; o >>= 1) v = fmaxf(v, __shfl_xor_sync(FULLM, v, o));
    return v;
}

// Dynamic select a[k] (runtime k) from a static register array: 31-SEL mux tree.
__device__ __forceinline__ float sel32(const float (&a)[32], int k) {
    float t16[16], t8[8], t4[4], t2[2];
    #pragma unroll
    for (int j = 0; j < 16; j++) t16[j] = (k & 16) ? a[j + 16] : a[j];
    #pragma unroll
    for (int j = 0; j < 8;  j++) t8[j]  = (k & 8)  ? t16[j + 8] : t16[j];
    #pragma unroll
    for (int j = 0; j < 4;  j++) t4[j]  = (k & 4)  ? t8[j + 4]  : t8[j];
    #pragma unroll
    for (int j = 0; j < 2;  j++) t2[j]  = (k & 2)  ? t4[j + 2]  : t4[j];
    return (k & 1) ? t2[1] : t2[0];
}

// Sturm count for 32x32 tridiagonal (diag dS, squared offdiag e2S): #eigs < x.
__device__ __forceinline__ int sturm32(const float* __restrict__ dS,
                                       const float* __restrict__ e2S, float x) {
    float dp = dS[0] - x;
    int cnt = (dp < 0.f) ? 1 : 0;
    #pragma unroll
    for (int i = 1; i < 32; i++) {
        float den = copysignf(fmaxf(fabsf(dp), 1e-25f), dp);
        dp = (dS[i] - x) - __fdividef(e2S[i - 1], den);
        cnt += (dp < 0.f) ? 1 : 0;
    }
    return cnt;
}

// ---------------------------------------------------------------------------
// Kernel 2: per-batch — prologue (256 threads): reduce partials (fp64),
// center+normalize to C (fp32). Warp 0 then: Householder tridiagonalization
// (register rows; v/q broadcast via smem LDS.128, not shfl) + multi-point
// Sturm bisection for lambda 0/7/8.
// ---------------------------------------------------------------------------
__global__ void __launch_bounds__(256) eig_kernel(float* __restrict__ out, int n) {
    const int b = blockIdx.x;
    if (b >= BATCH) return;
    const int tid  = threadIdx.x;
    const int lane = tid & 31;
    const int wid  = tid >> 5;

    __shared__ double Gs[W][W + 1];
    __shared__ double rsum[W];
    __shared__ double Ssum;
    __shared__ double traceSh;
    __shared__ float  dinv[W];
    __shared__ float  Abuf[W][W + 1];
    __shared__ float  dS[W];                     // tridiagonal diag
    __shared__ float  e2S[W];                    // offdiag^2 (0..30; [31]=0)
    __shared__ float  eaS[W];                    // |offdiag| (0..30; [31]=0)
    __shared__ __align__(16) float vSh[W];       // Householder v broadcast
    __shared__ __align__(16) float qSh[W];       // Householder q broadcast

    // --- reduce chunk partials in double, mirror to full symmetric matrix ---
    for (int t = tid; t < NPAIR; t += 256) {
        double g = 0.0;
        #pragma unroll
        for (int c = 0; c < NCH; c++) g += (double)g_part[b][c][t];
        int i = 0, rem = t;
        while (rem >= W - i) { rem -= W - i; i++; }
        int j = i + rem;
        Gs[i][j] = g;
        Gs[j][i] = g;
    }
    __syncthreads();

    if (tid < W) {
        double r = 0.0;
        #pragma unroll
        for (int j = 0; j < W; j++) r += Gs[tid][j];
        rsum[tid] = r;
    }
    __syncthreads();
    if (tid == 0) {
        double s = 0.0;
        #pragma unroll
        for (int i = 0; i < W; i++) s += rsum[i];
        Ssum = s;
    }
    __syncthreads();

    const double Sq = Ssum * (1.0 / 1024.0);   // S / 32^2

    if (tid < W) {
        double di = Gs[tid][tid] - rsum[tid] * (1.0 / 16.0) + Sq;
        if (di < 0.0) di = 0.0;
        dinv[tid] = (float)(1.0 / (sqrt(di) + 1e-8));
    }
    __syncthreads();

    {
        #pragma unroll
        for (int e = 0; e < 4; e++) {
            int idx = tid + e * 256;
            int k = idx >> 5, l = idx & 31;
            double gc = Gs[k][l] - rsum[k] * (1.0 / 32.0) - rsum[l] * (1.0 / 32.0) + Sq;
            Abuf[k][l] = (float)gc * dinv[k] * dinv[l];
        }
    }
    __syncthreads();
    if (tid == 0) {
        double tr = 0.0;
        #pragma unroll
        for (int i = 0; i < W; i++) tr += (double)Abuf[i][i];
        traceSh = tr;
    }
    __syncthreads();

    if (wid != 0) return;   // warps 1..7 retire; warp 0 owns the eigensolve

    // ====================== Householder tridiagonalization ==================
    // Lane i holds row i of A in registers a[0..31] (static indices only).
    float a[32];
    #pragma unroll
    for (int j = 0; j < 32; j++) a[j] = Abuf[lane][j];

    const float4* vSh4 = reinterpret_cast<const float4*>(vSh);
    const float4* qSh4 = reinterpret_cast<const float4*>(qSh);

    #pragma unroll 1
    for (int k = 0; k < 30; k++) {
        const int m = k + 1;
        // column k: x_i = A[i][k] = own row element k (mux tree, runtime k)
        float x = sel32(a, k);
        if (lane < m) x = 0.f;
        float sig = wsum32(x * x);
        float x0  = __shfl_sync(FULLM, x, m);
        float nrm = sqrtf(sig);
        float alpha = -copysignf(nrm, x0);
        // beta = 2 / v^T v ;  v^T v = 2*(sig + |x0|*nrm)  (no cancellation)
        float beta = (sig > 1e-30f) ? __fdividef(1.f, sig + fabsf(x0) * nrm) : 0.f;
        float vi = (lane == m) ? x - alpha : x;

        // publish v: 1 STS, read back as 8 x LDS.128 broadcast
        vSh[lane] = vi;
        __syncwarp();

        // p = beta * (A v), 4 accumulators; v_j = 0 for j < m
        float p0 = 0.f, p1 = 0.f, p2 = 0.f, p3 = 0.f;
        #pragma unroll
        for (int c = 0; c < 8; c++) {
            float4 v4 = vSh4[c];
            p0 = fmaf(a[4 * c + 0], v4.x, p0);
            p1 = fmaf(a[4 * c + 1], v4.y, p1);
            p2 = fmaf(a[4 * c + 2], v4.z, p2);
            p3 = fmaf(a[4 * c + 3], v4.w, p3);
        }
        float p = ((p0 + p1) + (p2 + p3));
        p = (lane >= m) ? p * beta : 0.f;

        float vtp = wsum32(vi * p);
        float Kc  = 0.5f * beta * vtp;
        float q   = p - Kc * vi;

        // publish q
        qSh[lane] = q;
        __syncwarp();

        // A -= v q^T + q v^T  (chunked; independent across j)
        #pragma unroll
        for (int c = 0; c < 8; c++) {
            float4 v4 = vSh4[c];
            float4 q4 = qSh4[c];
            a[4 * c + 0] = fmaf(-vi, q4.x, fmaf(-q, v4.x, a[4 * c + 0]));
            a[4 * c + 1] = fmaf(-vi, q4.y, fmaf(-q, v4.y, a[4 * c + 1]));
            a[4 * c + 2] = fmaf(-vi, q4.z, fmaf(-q, v4.z, a[4 * c + 2]));
            a[4 * c + 3] = fmaf(-vi, q4.w, fmaf(-q, v4.w, a[4 * c + 3]));
        }
        __syncwarp();   // vSh/qSh reused next iteration

        if (lane == 0) { e2S[k] = alpha * alpha; eaS[k] = fabsf(alpha); }
    }
    {   // last offdiagonal e_30 = A[30][31]
        float e30 = __shfl_sync(FULLM, a[31], 30);
        if (lane == 0) {
            e2S[30] = e30 * e30; eaS[30] = fabsf(e30);
            e2S[31] = 0.f;       eaS[31] = 0.f;
        }
    }
    dS[lane] = sel32(a, lane);   // diagonal
    __syncwarp();

    // ====================== multi-point Sturm bisection =====================
    // Gershgorin bracket
    float eprev = (lane > 0) ? eaS[lane - 1] : 0.f;
    float rad   = eaS[lane] + eprev;
    float lo = wmin32(dS[lane] - rad);
    float hi = wmax32(dS[lane] + rad);

    // 3 targets x 10 lanes: ascending eigen indices 31 (e0), 24 (e7), 23 (e8).
    int g = lane / 10; if (g > 2) g = 2;
    const int m = lane - g * 10;                 // 0..9 (lanes 30,31 ignored)
    const int idx = (g == 0) ? 31 : (g == 1) ? 24 : 23;

    #pragma unroll 1
    for (int r = 0; r < 8; r++) {
        float w  = (hi - lo) * (1.0f / 11.0f);
        float xx = lo + w * (float)(m + 1);
        int   cnt  = sturm32(dS, e2S, xx);
        unsigned bal = __ballot_sync(FULLM, cnt <= idx);   // x left of lambda_idx
        unsigned gb  = (bal >> (g * 10)) & 0x3FFu;
        int mstar = 31 - __clz(gb);                        // -1..9
        lo = lo + w * (float)(mstar + 1);
        hi = lo + w;
    }
    float lam = 0.5f * (lo + hi);
    float e0 = __shfl_sync(FULLM, lam, 0);
    float e7 = __shfl_sync(FULLM, lam, 10);
    float e8 = __shfl_sync(FULLM, lam, 20);

    if (lane == 0) {
        float gap   = e7 - e8;
        float decay = (e0 - e8) * (1.0f / 9.0f);
        float lmin  = e8 + 1e-8f;
        float topo  = gap / (decay + 1e-8f);
        if (topo < 0.f) topo = 0.f;
        float geo   = lmin / ((float)traceSh + 1e-8f);
        float gcve  = topo + geo;
        out[b]         = gcve;   // gcve_scores
        out[n + b]     = 0.0f;   // fracture_scores
        out[2 * n + b] = gcve;   // total_pressure
    }
}

// ---------------------------------------------------------------------------
extern "C" void kernel_launch(void* const* d_in, const int* in_sizes, int n_in,
                              void* d_out, int out_size) {
    const float* h = (const float*)d_in[0];
    float* out = (float*)d_out;
    int n = out_size / 3;   // 32

    dim3 g1(NCH, BATCH);
    gram_kernel<<<g1, 544>>>(h);
    eig_kernel<<<148, 256>>>(out, n);   // blocks >= 32 exit immediately
}